// round 1
// baseline (speedup 1.0000x reference)
#include <cuda_runtime.h>
#include <cuda_bf16.h>
#include <math.h>

// Problem constants
#define NN 100000
#define DD 512
#define KK 256

// GEMM1 tile
#define BM 64
#define BK 16

// GEMM2 tile
#define KT 128
#define DT 128
#define BN2 16
#define NSPLIT 32
#define NPS (NN / NSPLIT)   // 3125

// rsum splits
#define RSPLIT 128
#define RCHUNK ((NN + RSPLIT - 1) / RSPLIT)  // 782

// ---------------- scratch (device globals; no allocations allowed) -----------
__device__ float g_data[(size_t)NN * DD];          // normalized data, 204.8 MB
__device__ float g_mu[KK * DD];                    // current (unnormalized) mu
__device__ float g_mun[KK * DD];                   // normalized mu
__device__ float g_part[NSPLIT][KK * DD];          // GEMM2 partials, 16.8 MB
__device__ float g_rsum_part[RSPLIT][KK];
__device__ float g_rsum[KK];

// ---------------- row-normalize kernels (D=512, 128 threads, float4) ---------
__device__ __forceinline__ float block_sumsq_512(float4 v) {
    float ss = v.x * v.x + v.y * v.y + v.z * v.z + v.w * v.w;
    #pragma unroll
    for (int off = 16; off > 0; off >>= 1)
        ss += __shfl_xor_sync(0xffffffffu, ss, off);
    __shared__ float wsum[4];
    if ((threadIdx.x & 31) == 0) wsum[threadIdx.x >> 5] = ss;
    __syncthreads();
    return wsum[0] + wsum[1] + wsum[2] + wsum[3];
}

__global__ void norm_data_kernel(const float* __restrict__ in) {
    size_t row = blockIdx.x;
    const float4* ip = (const float4*)(in + row * DD);
    float4 v = ip[threadIdx.x];
    float tot = block_sumsq_512(v);
    float inv = 1.0f / (sqrtf(tot) + 1e-6f);
    float4 o = make_float4(v.x * inv, v.y * inv, v.z * inv, v.w * inv);
    ((float4*)(g_data + row * DD))[threadIdx.x] = o;
}

__global__ void norm_mu_kernel() {
    size_t row = blockIdx.x;
    const float4* ip = (const float4*)(g_mu + row * DD);
    float4 v = ip[threadIdx.x];
    float tot = block_sumsq_512(v);
    float inv = 1.0f / (sqrtf(tot) + 1e-6f);
    float4 o = make_float4(v.x * inv, v.y * inv, v.z * inv, v.w * inv);
    ((float4*)(g_mun + row * DD))[threadIdx.x] = o;
}

__global__ void copy_init_kernel(const float* __restrict__ src) {
    int i = blockIdx.x * blockDim.x + threadIdx.x;
    if (i < KK * DD) g_mu[i] = src[i];
}

// ---------------- GEMM1 + softmax:  r = softmax(T * data @ mu_n^T) -----------
// Block: 64 rows x 256 cols (all K). 256 threads, 8x8 micro-tiles.
// warp w == row-group w: rows w*8..w*8+7, lanes cover all 256 cols (8 each).
__global__ __launch_bounds__(256, 2)
void gemm1_softmax_kernel(const float* __restrict__ tempp, float* __restrict__ rout) {
    __shared__ float As[BK][BM + 4];   // transposed A tile, 16B-aligned rows (68*4=272)
    __shared__ float Bs[BK][KK];       // transposed B tile (mu_n^T)

    const int t = threadIdx.x;
    const int rowbase = blockIdx.x * BM;
    const int rg = t >> 5;             // warp id = row group
    const int cg = t & 31;
    const int row0 = rg * 8;
    const int col0 = cg * 8;

    float acc[8][8] = {};

    const int arow = t >> 2;
    const int ac = (t & 3) * 4;

    for (int k0 = 0; k0 < DD; k0 += BK) {
        // A tile: 64x16, one float4 per thread
        float4 av = make_float4(0.f, 0.f, 0.f, 0.f);
        int gr = rowbase + arow;
        if (gr < NN)
            av = *(const float4*)(g_data + (size_t)gr * DD + k0 + ac);
        As[ac + 0][arow] = av.x;
        As[ac + 1][arow] = av.y;
        As[ac + 2][arow] = av.z;
        As[ac + 3][arow] = av.w;
        // B tile: mu_n rows j=t, 4 float4 each -> Bs[kk][j]
        #pragma unroll
        for (int l = 0; l < 4; l++) {
            float4 bv = *(const float4*)(g_mun + (size_t)t * DD + k0 + l * 4);
            Bs[l * 4 + 0][t] = bv.x;
            Bs[l * 4 + 1][t] = bv.y;
            Bs[l * 4 + 2][t] = bv.z;
            Bs[l * 4 + 3][t] = bv.w;
        }
        __syncthreads();

        #pragma unroll
        for (int kk = 0; kk < BK; kk++) {
            __align__(16) float a[8];
            __align__(16) float b[8];
            *(float4*)&a[0] = *(const float4*)&As[kk][row0];
            *(float4*)&a[4] = *(const float4*)&As[kk][row0 + 4];
            *(float4*)&b[0] = *(const float4*)&Bs[kk][col0];
            *(float4*)&b[4] = *(const float4*)&Bs[kk][col0 + 4];
            #pragma unroll
            for (int i = 0; i < 8; i++)
                #pragma unroll
                for (int j = 0; j < 8; j++)
                    acc[i][j] = fmaf(a[i], b[j], acc[i][j]);
        }
        __syncthreads();
    }

    // softmax epilogue: each warp owns 8 full rows
    const float tv = tempp[0];
    #pragma unroll
    for (int i = 0; i < 8; i++) {
        int grow = rowbase + row0 + i;
        if (grow >= NN) continue;    // uniform within warp
        float m = acc[i][0];
        #pragma unroll
        for (int j = 1; j < 8; j++) m = fmaxf(m, acc[i][j]);
        #pragma unroll
        for (int off = 16; off > 0; off >>= 1)
            m = fmaxf(m, __shfl_xor_sync(0xffffffffu, m, off));
        __align__(16) float e[8];
        float s = 0.f;
        #pragma unroll
        for (int j = 0; j < 8; j++) {
            e[j] = expf(tv * (acc[i][j] - m));
            s += e[j];
        }
        #pragma unroll
        for (int off = 16; off > 0; off >>= 1)
            s += __shfl_xor_sync(0xffffffffu, s, off);
        float inv = 1.0f / s;
        #pragma unroll
        for (int j = 0; j < 8; j++) e[j] *= inv;
        float* rp = rout + (size_t)grow * KK + col0;
        *(float4*)&rp[0] = *(float4*)&e[0];
        *(float4*)&rp[4] = *(float4*)&e[4];
    }
}

// ---------------- rsum: column sums of r (deterministic 2-stage) -------------
__global__ void rsum_part_kernel(const float* __restrict__ r) {
    int sblk = blockIdx.x;
    int col = threadIdx.x;
    int n0 = sblk * RCHUNK;
    int n1 = n0 + RCHUNK; if (n1 > NN) n1 = NN;
    float s0 = 0.f, s1 = 0.f, s2 = 0.f, s3 = 0.f;
    int n = n0;
    for (; n + 4 <= n1; n += 4) {
        s0 += r[(size_t)(n + 0) * KK + col];
        s1 += r[(size_t)(n + 1) * KK + col];
        s2 += r[(size_t)(n + 2) * KK + col];
        s3 += r[(size_t)(n + 3) * KK + col];
    }
    for (; n < n1; n++) s0 += r[(size_t)n * KK + col];
    g_rsum_part[sblk][col] = (s0 + s1) + (s2 + s3);
}

__global__ void rsum_reduce_kernel() {
    int col = threadIdx.x;
    float s = 0.f;
    #pragma unroll 8
    for (int p = 0; p < RSPLIT; p++) s += g_rsum_part[p][col];
    g_rsum[col] = s;
}

// ---------------- GEMM2: mu_part = r^T @ data over an N split ----------------
// Grid (kblk:2, dblk:4, s:32). Block: 128(K) x 128(D) out tile, 256 threads,
// 8x8 micro-tiles, loops its 3125-row N split in 16-row chunks.
__global__ __launch_bounds__(256, 2)
void gemm2_kernel(const float* __restrict__ r) {
    __shared__ float Rs[BN2][KT];
    __shared__ float Ds[BN2][DT];

    const int kblk = blockIdx.x;
    const int dblk = blockIdx.y;
    const int s = blockIdx.z;
    const int t = threadIdx.x;
    const int kg = t >> 4;
    const int dg = t & 15;
    const int row0 = kg * 8;
    const int col0 = dg * 8;

    float acc[8][8] = {};

    const int nbase0 = s * NPS;
    const int nend = nbase0 + NPS;

    for (int nb = nbase0; nb < nend; nb += BN2) {
        #pragma unroll
        for (int l = 0; l < 2; l++) {
            int id = t + l * 256;
            int nr = id >> 5;
            int c = (id & 31) * 4;
            int gn = nb + nr;
            float4 rv = make_float4(0.f, 0.f, 0.f, 0.f);
            float4 dv = make_float4(0.f, 0.f, 0.f, 0.f);
            if (gn < nend) {
                rv = *(const float4*)(r + (size_t)gn * KK + kblk * KT + c);
                dv = *(const float4*)(g_data + (size_t)gn * DD + dblk * DT + c);
            }
            *(float4*)&Rs[nr][c] = rv;
            *(float4*)&Ds[nr][c] = dv;
        }
        __syncthreads();

        #pragma unroll
        for (int nn = 0; nn < BN2; nn++) {
            __align__(16) float a[8];
            __align__(16) float b[8];
            *(float4*)&a[0] = *(const float4*)&Rs[nn][row0];
            *(float4*)&a[4] = *(const float4*)&Rs[nn][row0 + 4];
            *(float4*)&b[0] = *(const float4*)&Ds[nn][col0];
            *(float4*)&b[4] = *(const float4*)&Ds[nn][col0 + 4];
            #pragma unroll
            for (int i = 0; i < 8; i++)
                #pragma unroll
                for (int j = 0; j < 8; j++)
                    acc[i][j] = fmaf(a[i], b[j], acc[i][j]);
        }
        __syncthreads();
    }

    float* p = g_part[s];
    #pragma unroll
    for (int i = 0; i < 8; i++) {
        float* pr = p + (size_t)(kblk * KT + row0 + i) * DD + dblk * DT + col0;
        *(float4*)&pr[0] = *(float4*)&acc[i][0];
        *(float4*)&pr[4] = *(float4*)&acc[i][4];
    }
}

// ---------------- finalize mu: sum partials, divide by rsum ------------------
__global__ void mu_final_kernel(float* __restrict__ extout, int write_ext) {
    int tid = blockIdx.x * blockDim.x + threadIdx.x;
    if (tid >= KK * DD) return;
    int k = tid >> 9;   // /512
    float sum = 0.f;
    #pragma unroll 8
    for (int p = 0; p < NSPLIT; p++) sum += g_part[p][tid];
    float v = sum / g_rsum[k];
    g_mu[tid] = v;
    if (write_ext) extout[tid] = v;
}

// ---------------- launch ------------------------------------------------------
extern "C" void kernel_launch(void* const* d_in, const int* in_sizes, int n_in,
                              void* d_out, int out_size) {
    const float* embeds = (const float*)d_in[0];
    const float* temp   = (const float*)d_in[1];
    const float* init   = (const float*)d_in[2];
    float* out_mu = (float*)d_out;                 // [K*D]
    float* out_r  = (float*)d_out + KK * DD;       // [N*K]; also used as r scratch

    norm_data_kernel<<<NN, 128>>>(embeds);
    copy_init_kernel<<<(KK * DD + 255) / 256, 256>>>(init);

    const int nblk1 = (NN + BM - 1) / BM;          // 1563
    for (int it = 0; it < 11; it++) {
        norm_mu_kernel<<<KK, 128>>>();
        gemm1_softmax_kernel<<<nblk1, 256>>>(temp, out_r);
        rsum_part_kernel<<<RSPLIT, KK>>>(out_r);
        rsum_reduce_kernel<<<1, KK>>>();
        gemm2_kernel<<<dim3(2, 4, NSPLIT), 256>>>(out_r);
        mu_final_kernel<<<(KK * DD + 255) / 256, 256>>>(out_mu, it == 10 ? 1 : 0);
    }
}